// round 12
// baseline (speedup 1.0000x reference)
#include <cuda_runtime.h>
#include <cuda_fp16.h>
#include <cuda_bf16.h>
#include <cstdint>

#define N_NODES 50000
#define N_EDGES 800000
#define N_GRAPHS 64
#define HEADS 8
#define NEG_SLOPE 0.2f
#define FULLM 0xffffffffu

// ---------------- scratch (device globals; no allocations allowed) ----------
static __device__ float  g_xp[(size_t)N_NODES * 256];
static __device__ __half g_xph[(size_t)N_NODES * 256];
static __device__ float  g_h[(size_t)N_NODES * 256];
static __device__ __half g_hh[(size_t)N_NODES * 256];
static __device__ float  g_xt[(size_t)N_NODES * 32];
static __device__ float  g_w1t[256 * 32];
static __device__ float  g_w2t[256 * 256];
static __device__ float  g_Bw[2048 * 256];               // Bw2[k*256+d]
static __device__ float  g_als[N_NODES * HEADS];
static __device__ float  g_ald[N_NODES * HEADS];
static __device__ float  g_als3[N_NODES * HEADS];        // layer-3 logits (separate: no WAR race)
static __device__ float  g_ald3[N_NODES * HEADS];
static __device__ int    g_deg[N_NODES];
static __device__ int    g_rowptr[N_NODES + 1];
static __device__ int    g_cursor[N_NODES];
static __device__ int    g_csrc[N_EDGES];
static __device__ float  g_pool[N_GRAPHS * 2048];
static __device__ float  g_wts[HEADS * 256];
static __device__ float  g_wtd[HEADS * 256];
static __device__ unsigned long long g_flag[64];         // chained-scan flags (reader resets)

__device__ __forceinline__ float leakyf(float x) { return x > 0.f ? x : NEG_SLOPE * x; }
__device__ __forceinline__ float eluf(float x)   { return x > 0.f ? x : (__expf(x) - 1.f); }

__device__ __forceinline__ uint32_t f2tf32(float x) {
    uint32_t r; asm("cvt.rna.tf32.f32 %0, %1;" : "=r"(r) : "f"(x)); return r;
}
__device__ __forceinline__ float roundtf(float x) { return __uint_as_float(f2tf32(x)); }

__device__ __forceinline__ void mma_tf32(float* c, const uint32_t* a, const uint32_t* b) {
    asm volatile(
        "mma.sync.aligned.m16n8k8.row.col.f32.tf32.tf32.f32 "
        "{%0,%1,%2,%3}, {%4,%5,%6,%7}, {%8,%9}, {%0,%1,%2,%3};\n"
        : "+f"(c[0]), "+f"(c[1]), "+f"(c[2]), "+f"(c[3])
        : "r"(a[0]), "r"(a[1]), "r"(a[2]), "r"(a[3]), "r"(b[0]), "r"(b[1]));
}
__device__ __forceinline__ void cp16(uint32_t sa, const float* g, uint32_t sz) {
    asm volatile("cp.async.cg.shared.global [%0], [%1], 16, %2;\n" :: "r"(sa), "l"(g), "r"(sz));
}

// ---------------- fused preprocessing (blockIdx-range dispatch) --------------
#define PRE_BLOCKS 9302
__global__ void k_pre(const float* __restrict__ x,  const float* __restrict__ W1,
                      const float* __restrict__ W2, const float* __restrict__ W3,
                      const float* __restrict__ as3, const float* __restrict__ ad3)
{
    int b = blockIdx.x, t = threadIdx.x;
    if (b < 196) {
        int i = b * 256 + t;
        if (i < N_NODES) g_deg[i] = 0;
    } else if (b < 708) {
        int i = (b - 196) * 256 + t;
        g_pool[i] = 0.f;
    } else if (b < 6958) {
        int i = (b - 708) * 256 + t;
        g_xt[i] = roundtf(x[i]);
    } else if (b < 6990) {
        int i = (b - 6958) * 256 + t;
        g_w1t[i] = roundtf(W1[i]);
    } else if (b < 7246) {
        int i = (b - 6990) * 256 + t;
        g_w2t[i] = roundtf(W2[i]);
    } else if (b < 9294) {
        int i = (b - 7246) * 256 + t;     // i = k*256 + d
        int k = i >> 8, d = i & 255;
        int h = k >> 8, j = k & 255;
        g_Bw[i] = roundtf(W3[(size_t)(h * 256 + d) * 256 + j]);
    } else {
        int idx = (b - 9294) * 256 + t;   // 2048 outputs
        int h = idx >> 8, k = idx & 255;
        float s1 = 0.f, s2 = 0.f;
        for (int d = 0; d < 256; d++) {
            float w = W3[(size_t)(h * 256 + d) * 256 + k];
            s1 += as3[h * 256 + d] * w;
            s2 += ad3[h * 256 + d] * w;
        }
        g_wts[idx] = s1;
        g_wtd[idx] = s2;
    }
}

// ---------------- CSR build --------------------------------------------------
__global__ void k_hist(const int* __restrict__ dst) {
    int e = blockIdx.x * blockDim.x + threadIdx.x;
    if (e < N_EDGES) atomicAdd(&g_deg[dst[e]], 1);
}

// chained multi-block scan: 49 blocks x 1024, co-resident; decoupled chain
#define SCAN_BLOCKS 49
__global__ void k_scan_chain() {
    int b = blockIdx.x, t = threadIdx.x, lane = t & 31, w = t >> 5;
    __shared__ int wsum[32];
    __shared__ int carry_s;
    int i = b * 1024 + t;
    int v = (i < N_NODES) ? g_deg[i] : 0;
    int x = v;
#pragma unroll
    for (int off = 1; off < 32; off <<= 1) {
        int y = __shfl_up_sync(FULLM, x, off);
        if (lane >= off) x += y;
    }
    if (lane == 31) wsum[w] = x;
    __syncthreads();
    if (w == 0) {
        int s = wsum[lane];
#pragma unroll
        for (int off = 1; off < 32; off <<= 1) {
            int y = __shfl_up_sync(FULLM, s, off);
            if (lane >= off) s += y;
        }
        wsum[lane] = s;
    }
    __syncthreads();
    int incl = x + ((w > 0) ? wsum[w - 1] : 0);
    int btotal = wsum[31];
    if (t == 0) {
        int c = 0;
        if (b > 0) {
            unsigned long long fv;
            do { fv = atomicAdd(&g_flag[b - 1], 0ULL); } while (!(fv >> 32));
            c = (int)(fv & 0xffffffffULL);
            atomicExch(&g_flag[b - 1], 0ULL);     // reset for next graph replay
        }
        if (b < SCAN_BLOCKS - 1)
            atomicExch(&g_flag[b], (1ULL << 32) | (unsigned long long)(unsigned)(c + btotal));
        carry_s = c;
    }
    __syncthreads();
    int c = carry_s;
    if (i < N_NODES) { g_rowptr[i] = c + incl - v; g_cursor[i] = c + incl - v; }
    if (b == SCAN_BLOCKS - 1 && t == 0) g_rowptr[N_NODES] = N_EDGES;
}

__global__ void k_scatter(const int* __restrict__ src, const int* __restrict__ dst) {
    int e = blockIdx.x * blockDim.x + threadIdx.x;
    if (e < N_EDGES) {
        int d = dst[e];
        int pos = atomicAdd(&g_cursor[d], 1);
        g_csrc[pos] = src[e];
    }
}

// ---------------- pipelined legacy tf32 GEMM: C[M,256]=A[M,K]*B[256,K]^T -----
#define GSM_A (128 * 32)
#define GSM_B (256 * 32)
#define GSM_BYTES (3 * (GSM_A + GSM_B) * 4)

__global__ __launch_bounds__(256, 1) void k_mma2(
    const float* __restrict__ A, const float* __restrict__ B,
    float* __restrict__ C, __half* __restrict__ Ch,
    const float* __restrict__ asv, const float* __restrict__ adv,
    float* __restrict__ als_out, float* __restrict__ ald_out,
    int M, int K)
{
    extern __shared__ float smem[];
    float* As = smem;
    float* Bs = smem + 3 * GSM_A;
    uint32_t As_u = (uint32_t)__cvta_generic_to_shared(As);
    uint32_t Bs_u = (uint32_t)__cvta_generic_to_shared(Bs);

    int tid = threadIdx.x;
    int lane = tid & 31, wid = tid >> 5;
    int qm = lane >> 2, qk = lane & 3;
    int wm = (wid >> 2) * 64;
    int wn = (wid & 3) * 64;
    int m0 = blockIdx.x * 128;

    float acc[4][8][4];
#pragma unroll
    for (int mt = 0; mt < 4; mt++)
#pragma unroll
        for (int nt = 0; nt < 8; nt++)
#pragma unroll
            for (int r = 0; r < 4; r++) acc[mt][nt][r] = 0.f;

    auto stage = [&](int s, int k0) {
#pragma unroll
        for (int i = 0; i < 4; i++) {
            int idx = tid + i * 256;
            int r = idx >> 3, cc = idx & 7;
            int gm = m0 + r;
            const float* srcp = A + (size_t)(gm < M ? gm : (M - 1)) * K + k0 + cc * 4;
            uint32_t dstp = As_u + (uint32_t)(s * GSM_A + r * 32 + ((cc ^ (r & 7)) << 2)) * 4u;
            cp16(dstp, srcp, (gm < M) ? 16u : 0u);
        }
#pragma unroll
        for (int i = 0; i < 8; i++) {
            int idx = tid + i * 256;
            int r = idx >> 3, cc = idx & 7;
            const float* srcp = B + (size_t)r * K + k0 + cc * 4;
            uint32_t dstp = Bs_u + (uint32_t)(s * GSM_B + r * 32 + ((cc ^ (r & 7)) << 2)) * 4u;
            cp16(dstp, srcp, 16u);
        }
    };

    int niter = K >> 5;
    stage(0, 0);
    asm volatile("cp.async.commit_group;");
    if (K > 32) stage(1, 32);
    asm volatile("cp.async.commit_group;");

    for (int i = 0; i < niter; i++) {
        asm volatile("cp.async.wait_group 1;");
        __syncthreads();
        int knext = (i + 2) << 5;
        if (knext < K) stage((i + 2) % 3, knext);
        asm volatile("cp.async.commit_group;");

        const float* Ab = As + (i % 3) * GSM_A;
        const float* Bb = Bs + (i % 3) * GSM_B;
#pragma unroll
        for (int ks = 0; ks < 4; ks++) {
            int lo  = (((2 * ks)     ^ qm) << 2) + qk;
            int hi2 = (((2 * ks + 1) ^ qm) << 2) + qk;
            uint32_t af[4][4], bf[8][2];
#pragma unroll
            for (int mt = 0; mt < 4; mt++) {
                int rm = wm + mt * 16 + qm;
                af[mt][0] = __float_as_uint(Ab[rm * 32 + lo]);
                af[mt][1] = __float_as_uint(Ab[(rm + 8) * 32 + lo]);
                af[mt][2] = __float_as_uint(Ab[rm * 32 + hi2]);
                af[mt][3] = __float_as_uint(Ab[(rm + 8) * 32 + hi2]);
            }
#pragma unroll
            for (int nt = 0; nt < 8; nt++) {
                int rn = wn + nt * 8 + qm;
                bf[nt][0] = __float_as_uint(Bb[rn * 32 + lo]);
                bf[nt][1] = __float_as_uint(Bb[rn * 32 + hi2]);
            }
#pragma unroll
            for (int mt = 0; mt < 4; mt++)
#pragma unroll
                for (int nt = 0; nt < 8; nt++)
                    mma_tf32(acc[mt][nt], af[mt], bf[nt]);
        }
        __syncthreads();
    }

    float2 asl[8], adl[8];
    bool do_al = (als_out != nullptr);
    if (do_al) {
#pragma unroll
        for (int nt = 0; nt < 8; nt++) {
            int gn = wn + nt * 8 + 2 * qk;
            asl[nt] = *(const float2*)(asv + gn);
            adl[nt] = *(const float2*)(adv + gn);
        }
    }
    int h0_ = wn >> 5;

#pragma unroll
    for (int mt = 0; mt < 4; mt++) {
        float pA[2][2] = {{0.f, 0.f}, {0.f, 0.f}};
        float pD[2][2] = {{0.f, 0.f}, {0.f, 0.f}};
#pragma unroll
        for (int nt = 0; nt < 8; nt++) {
            int gm = m0 + wm + mt * 16 + qm;
            int gn = wn + nt * 8 + 2 * qk;
            float v00 = acc[mt][nt][0], v01 = acc[mt][nt][1];
            float v10 = acc[mt][nt][2], v11 = acc[mt][nt][3];
            if (gm < M) {
                C[(size_t)gm * 256 + gn]     = v00;
                C[(size_t)gm * 256 + gn + 1] = v01;
                __half2 hv = __floats2half2_rn(v00, v01);
                *(__half2*)(Ch + (size_t)gm * 256 + gn) = hv;
            }
            if (gm + 8 < M) {
                C[(size_t)(gm + 8) * 256 + gn]     = v10;
                C[(size_t)(gm + 8) * 256 + gn + 1] = v11;
                __half2 hv = __floats2half2_rn(v10, v11);
                *(__half2*)(Ch + (size_t)(gm + 8) * 256 + gn) = hv;
            }
            if (do_al) {
                int hs = nt >> 2;
                pA[0][hs] += v00 * asl[nt].x + v01 * asl[nt].y;
                pA[1][hs] += v10 * asl[nt].x + v11 * asl[nt].y;
                pD[0][hs] += v00 * adl[nt].x + v01 * adl[nt].y;
                pD[1][hs] += v10 * adl[nt].x + v11 * adl[nt].y;
            }
        }
        if (do_al) {
#pragma unroll
            for (int r = 0; r < 2; r++)
#pragma unroll
                for (int hh2 = 0; hh2 < 2; hh2++) {
                    pA[r][hh2] += __shfl_xor_sync(FULLM, pA[r][hh2], 1);
                    pA[r][hh2] += __shfl_xor_sync(FULLM, pA[r][hh2], 2);
                    pD[r][hh2] += __shfl_xor_sync(FULLM, pD[r][hh2], 1);
                    pD[r][hh2] += __shfl_xor_sync(FULLM, pD[r][hh2], 2);
                }
            if (qk == 0) {
                int gm = m0 + wm + mt * 16 + qm;
                if (gm < M) {
                    als_out[(size_t)gm * 8 + h0_]     = pA[0][0];
                    als_out[(size_t)gm * 8 + h0_ + 1] = pA[0][1];
                    ald_out[(size_t)gm * 8 + h0_]     = pD[0][0];
                    ald_out[(size_t)gm * 8 + h0_ + 1] = pD[0][1];
                }
                if (gm + 8 < M) {
                    als_out[(size_t)(gm + 8) * 8 + h0_]     = pA[1][0];
                    als_out[(size_t)(gm + 8) * 8 + h0_ + 1] = pA[1][1];
                    ald_out[(size_t)(gm + 8) * 8 + h0_]     = pD[1][0];
                    ald_out[(size_t)(gm + 8) * 8 + h0_ + 1] = pD[1][1];
                }
            }
        }
    }
}

// ---------------- single-pass GAT layer; optional fused layer-3 logits -------
// layer-3 logits are written to SEPARATE buffers (g_als3/g_ald3) — no WAR race
// with the g_als/g_ald gathers in the edge loop.
__global__ void k_gat32(const float* __restrict__ xp, const __half* __restrict__ xph,
                        const float* __restrict__ bias,
                        float* __restrict__ out, __half* __restrict__ out_h,
                        int do_al3)
{
    int n = blockIdx.x * (blockDim.x >> 5) + (threadIdx.x >> 5);
    if (n >= N_NODES) return;
    int lane = threadIdx.x & 31;
    int hd = lane & 7;
    int h0 = lane >> 3;
    int lo = g_rowptr[n], hi = g_rowptr[n + 1];
    float adh = g_ald[n * HEADS + hd];

    float acc[8];
    float den;
    {
        float av = __expf(leakyf(g_als[n * HEADS + hd] + adh));
        den = av;
        float av0 = __shfl_sync(FULLM, av, h0);
        float av1 = __shfl_sync(FULLM, av, 4 + h0);
        float4 v0 = *(const float4*)(xp + (size_t)n * 256 + lane * 4);
        float4 v1 = *(const float4*)(xp + (size_t)n * 256 + 128 + lane * 4);
        acc[0] = av0 * v0.x; acc[1] = av0 * v0.y; acc[2] = av0 * v0.z; acc[3] = av0 * v0.w;
        acc[4] = av1 * v1.x; acc[5] = av1 * v1.y; acc[6] = av1 * v1.z; acc[7] = av1 * v1.w;
    }
    for (int p = lo; p < hi; p++) {
        int s = g_csrc[p];
        float av = __expf(leakyf(g_als[s * HEADS + hd] + adh));
        den += av;
        float av0 = __shfl_sync(FULLM, av, h0);
        float av1 = __shfl_sync(FULLM, av, 4 + h0);
        uint2 u0 = *(const uint2*)(xph + (size_t)s * 256 + lane * 4);
        uint2 u1 = *(const uint2*)(xph + (size_t)s * 256 + 128 + lane * 4);
        float2 fa = __half22float2(*(__half2*)&u0.x);
        float2 fb = __half22float2(*(__half2*)&u0.y);
        float2 fc = __half22float2(*(__half2*)&u1.x);
        float2 fd = __half22float2(*(__half2*)&u1.y);
        acc[0] += av0 * fa.x; acc[1] += av0 * fa.y; acc[2] += av0 * fb.x; acc[3] += av0 * fb.y;
        acc[4] += av1 * fc.x; acc[5] += av1 * fc.y; acc[6] += av1 * fd.x; acc[7] += av1 * fd.y;
    }
    float rn0 = 1.f / __shfl_sync(FULLM, den, h0);
    float rn1 = 1.f / __shfl_sync(FULLM, den, 4 + h0);
    float4 b0 = *(const float4*)(bias + lane * 4);
    float4 b1 = *(const float4*)(bias + 128 + lane * 4);
    float o0 = eluf(acc[0] * rn0 + b0.x), o1 = eluf(acc[1] * rn0 + b0.y);
    float o2 = eluf(acc[2] * rn0 + b0.z), o3 = eluf(acc[3] * rn0 + b0.w);
    float o4 = eluf(acc[4] * rn1 + b1.x), o5 = eluf(acc[5] * rn1 + b1.y);
    float o6 = eluf(acc[6] * rn1 + b1.z), o7 = eluf(acc[7] * rn1 + b1.w);
    *(float4*)(out + (size_t)n * 256 + lane * 4) =
        make_float4(roundtf(o0), roundtf(o1), roundtf(o2), roundtf(o3));
    *(float4*)(out + (size_t)n * 256 + 128 + lane * 4) =
        make_float4(roundtf(o4), roundtf(o5), roundtf(o6), roundtf(o7));
    if (out_h) {
        __half2 p01 = __floats2half2_rn(o0, o1), p23 = __floats2half2_rn(o2, o3);
        __half2 p45 = __floats2half2_rn(o4, o5), p67 = __floats2half2_rn(o6, o7);
        uint2 w0, w1;
        w0.x = *(uint32_t*)&p01; w0.y = *(uint32_t*)&p23;
        w1.x = *(uint32_t*)&p45; w1.y = *(uint32_t*)&p67;
        *(uint2*)(out_h + (size_t)n * 256 + lane * 4) = w0;
        *(uint2*)(out_h + (size_t)n * 256 + 128 + lane * 4) = w1;
    }
    if (do_al3) {
#pragma unroll
        for (int hd2 = 0; hd2 < HEADS; hd2++) {
            float4 wa = *(const float4*)(g_wts + hd2 * 256 + lane * 4);
            float4 wb = *(const float4*)(g_wts + hd2 * 256 + 128 + lane * 4);
            float4 da = *(const float4*)(g_wtd + hd2 * 256 + lane * 4);
            float4 db = *(const float4*)(g_wtd + hd2 * 256 + 128 + lane * 4);
            float s1 = o0 * wa.x + o1 * wa.y + o2 * wa.z + o3 * wa.w
                     + o4 * wb.x + o5 * wb.y + o6 * wb.z + o7 * wb.w;
            float s2 = o0 * da.x + o1 * da.y + o2 * da.z + o3 * da.w
                     + o4 * db.x + o5 * db.y + o6 * db.z + o7 * db.w;
#pragma unroll
            for (int o = 16; o; o >>= 1) {
                s1 += __shfl_down_sync(FULLM, s1, o);
                s2 += __shfl_down_sync(FULLM, s2, o);
            }
            if (lane == 0) {
                g_als3[n * HEADS + hd2] = s1;
                g_ald3[n * HEADS + hd2] = s2;
            }
        }
    }
}

// ---------------- layer-3: fused softmax+agg+pool (reads als3/ald3) ----------
__global__ void k_aggH_pool(const float* __restrict__ h, const __half* __restrict__ hh,
                            const int* __restrict__ batch)
{
    int n0 = blockIdx.x * 32;
    int t = threadIdx.x;   // 256
    __shared__ float a_sm[32][HEADS];
    __shared__ int s_sm[32];
    __shared__ float ad_s[HEADS], avs_s[HEADS], den_s[HEADS];
    int nend = min(n0 + 32, N_NODES);
    if (n0 >= N_NODES) return;
    float pacc[HEADS];
#pragma unroll
    for (int k = 0; k < HEADS; k++) pacc[k] = 0.f;
    int prevb = batch[n0];

    for (int n = n0; n < nend; n++) {
        int bn = batch[n];
        if (bn != prevb) {
#pragma unroll
            for (int k = 0; k < HEADS; k++) {
                atomicAdd(&g_pool[prevb * 2048 + k * 256 + t], pacc[k]);
                pacc[k] = 0.f;
            }
            prevb = bn;
        }
        __syncthreads();
        if (t < 8) {
            float ad = g_ald3[n * HEADS + t];
            ad_s[t] = ad;
            float av = __expf(leakyf(g_als3[n * HEADS + t] + ad));
            avs_s[t] = av;
            den_s[t] = av;
        }
        __syncthreads();
        int lo = g_rowptr[n], hi = g_rowptr[n + 1];
        float hv = h[(size_t)n * 256 + t];
        float acc[HEADS];
#pragma unroll
        for (int k = 0; k < HEADS; k++)
            acc[k] = avs_s[k] * hv;
        for (int p0 = lo; p0 < hi; p0 += 32) {
            int cnt = min(32, hi - p0);
            __syncthreads();
            if (t < cnt) s_sm[t] = g_csrc[p0 + t];
            __syncthreads();
            if (t < cnt * HEADS) {
                int jj = t >> 3, hd2 = t & 7;
                a_sm[jj][hd2] = __expf(leakyf(g_als3[s_sm[jj] * HEADS + hd2] + ad_s[hd2]));
            }
            __syncthreads();
            if (t < 8) {
                float dsum = 0.f;
                for (int jj = 0; jj < cnt; jj++) dsum += a_sm[jj][t];
                den_s[t] += dsum;
            }
            for (int jj = 0; jj < cnt; jj++) {
                float hv2 = __half2float(hh[(size_t)s_sm[jj] * 256 + t]);
#pragma unroll
                for (int k = 0; k < HEADS; k++)
                    acc[k] += a_sm[jj][k] * hv2;
            }
        }
        __syncthreads();
#pragma unroll
        for (int k = 0; k < HEADS; k++)
            pacc[k] += acc[k] / den_s[k];
    }
#pragma unroll
    for (int k = 0; k < HEADS; k++)
        atomicAdd(&g_pool[prevb * 2048 + k * 256 + t], pacc[k]);
}

// ---------------- final: pool-scale + W3 projection + classifier -------------
__device__ __forceinline__ int lower_bound_batch(const int* b, int val) {
    int lo = 0, hi = N_NODES;
    while (lo < hi) {
        int mid = (lo + hi) >> 1;
        if (b[mid] < val) lo = mid + 1; else hi = mid;
    }
    return lo;
}
__global__ __launch_bounds__(256) void k_final(
    const int* __restrict__ batch, const float* __restrict__ b3,
    const float* __restrict__ Wc1, const float* __restrict__ bc1,
    const float* __restrict__ Wc2, const float* __restrict__ bc2,
    float* __restrict__ out)
{
    int g = blockIdx.x;      // 64 blocks x 256 threads
    int t = threadIdx.x;
    __shared__ float ps[2048];
    __shared__ float gm[256];
    __shared__ float z[128];
    __shared__ float sc_s;
    if (t == 0) {
        int lo = lower_bound_batch(batch, g);
        int hi = lower_bound_batch(batch, g + 1);
        sc_s = 0.125f / (float)max(hi - lo, 1);
    }
    __syncthreads();
    float sc = sc_s;
#pragma unroll
    for (int i = 0; i < 8; i++)
        ps[i * 256 + t] = roundtf(g_pool[g * 2048 + i * 256 + t] * sc);
    __syncthreads();
    float acc = b3[t];
#pragma unroll 4
    for (int k = 0; k < 2048; k++)
        acc += ps[k] * g_Bw[k * 256 + t];
    gm[t] = acc;
    __syncthreads();
    if (t < 128) {
        float s = bc1[t];
        for (int k = 0; k < 256; k++) s += gm[k] * Wc1[t * 256 + k];
        z[t] = eluf(s);
    }
    __syncthreads();
    if (t < 2) {
        float o = bc2[t];
        for (int jj = 0; jj < 128; jj++) o += z[jj] * Wc2[t * 128 + jj];
        out[g * 2 + t] = o;
    }
}

// ---------------- launch -----------------------------------------------------
extern "C" void kernel_launch(void* const* d_in, const int* in_sizes, int n_in,
                              void* d_out, int out_size)
{
    const float* x      = (const float*)d_in[0];
    const int*   eidx   = (const int*)d_in[1];
    const int*   batch  = (const int*)d_in[2];
    const float* W1  = (const float*)d_in[3];
    const float* as1 = (const float*)d_in[4];
    const float* ad1 = (const float*)d_in[5];
    const float* b1  = (const float*)d_in[6];
    const float* W2  = (const float*)d_in[7];
    const float* as2 = (const float*)d_in[8];
    const float* ad2 = (const float*)d_in[9];
    const float* b2  = (const float*)d_in[10];
    const float* W3  = (const float*)d_in[11];
    const float* as3 = (const float*)d_in[12];
    const float* ad3 = (const float*)d_in[13];
    const float* b3  = (const float*)d_in[14];
    const float* Wc1 = (const float*)d_in[15];
    const float* bc1 = (const float*)d_in[16];
    const float* Wc2 = (const float*)d_in[17];
    const float* bc2 = (const float*)d_in[18];
    float* out = (float*)d_out;

    const int* src = eidx;
    const int* dst = eidx + N_EDGES;

    float*  xp  = nullptr; cudaGetSymbolAddress((void**)&xp,  g_xp);
    __half* xph = nullptr; cudaGetSymbolAddress((void**)&xph, g_xph);
    float*  h   = nullptr; cudaGetSymbolAddress((void**)&h,   g_h);
    __half* hh  = nullptr; cudaGetSymbolAddress((void**)&hh,  g_hh);
    float*  xt  = nullptr; cudaGetSymbolAddress((void**)&xt,  g_xt);
    float*  w1t = nullptr; cudaGetSymbolAddress((void**)&w1t, g_w1t);
    float*  w2t = nullptr; cudaGetSymbolAddress((void**)&w2t, g_w2t);
    float*  als = nullptr; cudaGetSymbolAddress((void**)&als, g_als);
    float*  ald = nullptr; cudaGetSymbolAddress((void**)&ald, g_ald);

    cudaFuncSetAttribute(k_mma2, cudaFuncAttributeMaxDynamicSharedMemorySize, GSM_BYTES);

    int gm = (N_NODES + 127) / 128;
    int nwb = (N_NODES + 7) / 8;

    k_pre<<<PRE_BLOCKS, 256>>>(x, W1, W2, W3, as3, ad3);                     // 1
    k_hist<<<(N_EDGES + 255) / 256, 256>>>(dst);                             // 2
    k_scan_chain<<<SCAN_BLOCKS, 1024>>>();                                   // 3
    k_scatter<<<(N_EDGES + 255) / 256, 256>>>(src, dst);                     // 4 (profiled)

    // ---- layer 1: GEMM (+fused als/ald), fused softmax+agg
    k_mma2<<<gm, 256, GSM_BYTES>>>(xt, w1t, xp, xph, as1, ad1, als, ald, N_NODES, 32);
    k_gat32<<<nwb, 256>>>(xp, xph, b1, h, nullptr, 0);

    // ---- layer 2 (+fused layer-3 logits into separate als3/ald3 buffers)
    k_mma2<<<gm, 256, GSM_BYTES>>>(h, w2t, xp, xph, as2, ad2, als, ald, N_NODES, 256);
    k_gat32<<<nwb, 256>>>(xp, xph, b2, h, hh, 1);

    // ---- layer 3: fused softmax+agg+pool, then fused projection+classifier
    k_aggH_pool<<<(N_NODES + 31) / 32, 256>>>(h, hh, batch);
    k_final<<<N_GRAPHS, 256>>>(batch, b3, Wc1, bc1, Wc2, bc2, out);
}